// round 3
// baseline (speedup 1.0000x reference)
#include <cuda_runtime.h>

#define N_NODES 100000
#define N_EDGES 1600000
#define HID 128

// ---------------- scratch (device globals; no allocation) ----------------
__device__ float g_cnt [N_NODES];
__device__ float g_agg1[N_NODES * 6];
__device__ float g_h1  [N_NODES * HID];
__device__ float g_agg2[N_NODES * HID];
__device__ float g_h2  [N_NODES * HID];
__device__ float g_p   [N_NODES * HID];   // h2 @ W_e1[0:128]
__device__ float g_q   [N_NODES * HID];   // h2 @ W_e1[128:256]

// ---------------- zero scratch accumulators ----------------
__global__ void k_zero() {
    int i = blockIdx.x * 256 + threadIdx.x;            // grid covers 3.2M float4
    float4 z = make_float4(0.f, 0.f, 0.f, 0.f);
    if (i < N_NODES * HID / 4) reinterpret_cast<float4*>(g_agg2)[i] = z;
    if (i < N_NODES * 6 / 4)   reinterpret_cast<float4*>(g_agg1)[i] = z;
    if (i < N_NODES / 4)       reinterpret_cast<float4*>(g_cnt)[i]  = z;
}

// ---------------- SAGE layer 1: scatter x[src] into agg1, count ----------------
__global__ void k_agg1(const float* __restrict__ x, const int* __restrict__ ei) {
    int e = blockIdx.x * 256 + threadIdx.x;
    int s = ei[e];
    int d = ei[N_EDGES + e];
    atomicAdd(&g_cnt[d], 1.0f);
#pragma unroll
    for (int k = 0; k < 6; k++)
        atomicAdd(&g_agg1[d * 6 + k], x[s * 6 + k]);
}

// ---------------- h1 = relu(x@W1r + mean1@W1n + b1) ----------------
__global__ void k_h1(const float* __restrict__ x,
                     const float* __restrict__ w1r, const float* __restrict__ w1n,
                     const float* __restrict__ b1) {
    int t = threadIdx.x;
    int node = blockIdx.x * 2 + (t >> 7);
    int j = t & 127;
    float inv = 1.0f / fmaxf(g_cnt[node], 1.0f);
    float acc = b1[j];
#pragma unroll
    for (int k = 0; k < 6; k++) {
        acc += x[node * 6 + k] * w1r[k * 128 + j]
             + g_agg1[node * 6 + k] * inv * w1n[k * 128 + j];
    }
    g_h1[node * 128 + j] = fmaxf(acc, 0.f);
}

// ---------------- scatter h1[src] into agg2 (warp per edge) ----------------
__global__ void k_agg2(const int* __restrict__ ei) {
    int w = blockIdx.x * 8 + (threadIdx.x >> 5);
    int lane = threadIdx.x & 31;
    int s = ei[w];
    int d = ei[N_EDGES + w];
    float4 v = *reinterpret_cast<const float4*>(&g_h1[s * 128 + lane * 4]);
    float* dst = &g_agg2[d * 128 + lane * 4];
    atomicAdd(dst + 0, v.x);
    atomicAdd(dst + 1, v.y);
    atomicAdd(dst + 2, v.z);
    atomicAdd(dst + 3, v.w);
}

// ---------------- h2 = relu(h1@W2r + mean2@W2n + b2), dual-A GEMM ----------------
__global__ void k_h2(const float* __restrict__ W1, const float* __restrict__ W2,
                     const float* __restrict__ bias) {
    __shared__ __align__(16) float As1[16][64];
    __shared__ __align__(16) float As2[16][64];
    __shared__ __align__(16) float Bs1[16][64];
    __shared__ __align__(16) float Bs2[16][64];
    int t = threadIdx.x;
    int row0 = blockIdx.x * 64;
    int col0 = blockIdx.y * 64;
    int lnode = t >> 2;            // 0..63
    int lk4   = (t & 3) * 4;       // 0,4,8,12
    int lkB   = t >> 4;            // 0..15
    int ljB   = (t & 15) * 4;
    int tx = t & 15, ty = t >> 4;
    float acc[4][4] = {};

    for (int k0 = 0; k0 < 128; k0 += 16) {
        int row = row0 + lnode;
        float4 a1, a2;
        if (row < N_NODES) {
            a1 = *reinterpret_cast<const float4*>(&g_h1[row * 128 + k0 + lk4]);
            a2 = *reinterpret_cast<const float4*>(&g_agg2[row * 128 + k0 + lk4]);
            float inv = 1.0f / fmaxf(g_cnt[row], 1.0f);
            a2.x *= inv; a2.y *= inv; a2.z *= inv; a2.w *= inv;
        } else {
            a1 = a2 = make_float4(0.f, 0.f, 0.f, 0.f);
        }
        As1[lk4 + 0][lnode] = a1.x; As1[lk4 + 1][lnode] = a1.y;
        As1[lk4 + 2][lnode] = a1.z; As1[lk4 + 3][lnode] = a1.w;
        As2[lk4 + 0][lnode] = a2.x; As2[lk4 + 1][lnode] = a2.y;
        As2[lk4 + 2][lnode] = a2.z; As2[lk4 + 3][lnode] = a2.w;
        *reinterpret_cast<float4*>(&Bs1[lkB][ljB]) =
            *reinterpret_cast<const float4*>(&W1[(k0 + lkB) * 128 + col0 + ljB]);
        *reinterpret_cast<float4*>(&Bs2[lkB][ljB]) =
            *reinterpret_cast<const float4*>(&W2[(k0 + lkB) * 128 + col0 + ljB]);
        __syncthreads();
#pragma unroll
        for (int kk = 0; kk < 16; kk++) {
            float4 a1v = *reinterpret_cast<float4*>(&As1[kk][ty * 4]);
            float4 a2v = *reinterpret_cast<float4*>(&As2[kk][ty * 4]);
            float4 b1v = *reinterpret_cast<float4*>(&Bs1[kk][tx * 4]);
            float4 b2v = *reinterpret_cast<float4*>(&Bs2[kk][tx * 4]);
            float ar1[4] = {a1v.x, a1v.y, a1v.z, a1v.w};
            float ar2[4] = {a2v.x, a2v.y, a2v.z, a2v.w};
            float br1[4] = {b1v.x, b1v.y, b1v.z, b1v.w};
            float br2[4] = {b2v.x, b2v.y, b2v.z, b2v.w};
#pragma unroll
            for (int i = 0; i < 4; i++)
#pragma unroll
                for (int jv = 0; jv < 4; jv++)
                    acc[i][jv] += ar1[i] * br1[jv] + ar2[i] * br2[jv];
        }
        __syncthreads();
    }

    int row = row0 + ty * 4;
    int col = col0 + tx * 4;
#pragma unroll
    for (int i = 0; i < 4; i++) {
        if (row + i < N_NODES) {
            float4 c;
            c.x = fmaxf(acc[i][0] + bias[col + 0], 0.f);
            c.y = fmaxf(acc[i][1] + bias[col + 1], 0.f);
            c.z = fmaxf(acc[i][2] + bias[col + 2], 0.f);
            c.w = fmaxf(acc[i][3] + bias[col + 3], 0.f);
            *reinterpret_cast<float4*>(&g_h2[(row + i) * 128 + col]) = c;
        }
    }
}

// ---------------- p = h2@W_a, q = h2@W_b (single-A dual-B GEMM) ----------------
__global__ void k_pq(const float* __restrict__ we1) {
    __shared__ __align__(16) float As[16][64];
    __shared__ __align__(16) float Bs1[16][64];
    __shared__ __align__(16) float Bs2[16][64];
    int t = threadIdx.x;
    int row0 = blockIdx.x * 64;
    int col0 = blockIdx.y * 64;
    int lnode = t >> 2;
    int lk4   = (t & 3) * 4;
    int lkB   = t >> 4;
    int ljB   = (t & 15) * 4;
    int tx = t & 15, ty = t >> 4;
    float acc1[4][4] = {};
    float acc2[4][4] = {};

    for (int k0 = 0; k0 < 128; k0 += 16) {
        int row = row0 + lnode;
        float4 a;
        if (row < N_NODES)
            a = *reinterpret_cast<const float4*>(&g_h2[row * 128 + k0 + lk4]);
        else
            a = make_float4(0.f, 0.f, 0.f, 0.f);
        As[lk4 + 0][lnode] = a.x; As[lk4 + 1][lnode] = a.y;
        As[lk4 + 2][lnode] = a.z; As[lk4 + 3][lnode] = a.w;
        // W_a = rows [0,128), W_b = rows [128,256) of w_e1 (260x128 row-major)
        *reinterpret_cast<float4*>(&Bs1[lkB][ljB]) =
            *reinterpret_cast<const float4*>(&we1[(k0 + lkB) * 128 + col0 + ljB]);
        *reinterpret_cast<float4*>(&Bs2[lkB][ljB]) =
            *reinterpret_cast<const float4*>(&we1[(128 + k0 + lkB) * 128 + col0 + ljB]);
        __syncthreads();
#pragma unroll
        for (int kk = 0; kk < 16; kk++) {
            float4 av  = *reinterpret_cast<float4*>(&As[kk][ty * 4]);
            float4 b1v = *reinterpret_cast<float4*>(&Bs1[kk][tx * 4]);
            float4 b2v = *reinterpret_cast<float4*>(&Bs2[kk][tx * 4]);
            float ar[4]  = {av.x, av.y, av.z, av.w};
            float br1[4] = {b1v.x, b1v.y, b1v.z, b1v.w};
            float br2[4] = {b2v.x, b2v.y, b2v.z, b2v.w};
#pragma unroll
            for (int i = 0; i < 4; i++)
#pragma unroll
                for (int jv = 0; jv < 4; jv++) {
                    acc1[i][jv] += ar[i] * br1[jv];
                    acc2[i][jv] += ar[i] * br2[jv];
                }
        }
        __syncthreads();
    }

    int row = row0 + ty * 4;
    int col = col0 + tx * 4;
#pragma unroll
    for (int i = 0; i < 4; i++) {
        if (row + i < N_NODES) {
            *reinterpret_cast<float4*>(&g_p[(row + i) * 128 + col]) =
                make_float4(acc1[i][0], acc1[i][1], acc1[i][2], acc1[i][3]);
            *reinterpret_cast<float4*>(&g_q[(row + i) * 128 + col]) =
                make_float4(acc2[i][0], acc2[i][1], acc2[i][2], acc2[i][3]);
        }
    }
}

// ---------------- fused edge MLP: 64 edges per block ----------------
// e1 = relu(p[src] + q[dst] + ea@W_c + b_e1)  -> smem transposed [j][edge]
// l2 = relu(e1 @ w_e2 + b_e2); out = l2 @ w_e3 + b_e3
__global__ void k_edge(const int* __restrict__ ei, const float* __restrict__ ea,
                       const float* __restrict__ we1, const float* __restrict__ be1,
                       const float* __restrict__ we2, const float* __restrict__ be2,
                       const float* __restrict__ we3, const float* __restrict__ be3,
                       float* __restrict__ out) {
    extern __shared__ __align__(16) float sm[];
    float* w2s = sm;                 // [128][64]         8192 floats
    float* e1t = sm + 8192;          // [128][68] padded  8704 floats
    float* wcs = e1t + 8704;         // [4][128]           512
    float* b1s = wcs + 512;          // 128
    float* b2s = b1s + 128;          // 64
    float* w3s = b2s + 64;           // 64
    float* eas = w3s + 64;           // [64][4]            256
    int*   srcs = reinterpret_cast<int*>(eas + 256);  // 64
    int*   dsts = srcs + 64;                          // 64

    int t = threadIdx.x;
    int e0 = blockIdx.x * 64;

    for (int i = t; i < 8192; i += 256) w2s[i] = we2[i];
    for (int i = t; i < 512;  i += 256) wcs[i] = we1[256 * 128 + i];
    if (t < 128) b1s[t] = be1[t];
    if (t < 64) { b2s[t] = be2[t]; w3s[t] = we3[t]; }
    if (t < 64)        srcs[t]      = ei[e0 + t];
    else if (t < 128)  dsts[t - 64] = ei[N_EDGES + e0 + (t - 64)];
    eas[t] = ea[e0 * 4 + t];        // 256 threads cover 64*4
    __syncthreads();

    // e1 phase: 128 threads per edge-pair, coalesced gathers of p/q rows
    {
        int j = t & 127;
        for (int el = t >> 7; el < 64; el += 2) {
            int s = srcs[el], d = dsts[el];
            float v = g_p[s * 128 + j] + g_q[d * 128 + j] + b1s[j];
            const float* eap = &eas[el * 4];
            v += eap[0] * wcs[j]       + eap[1] * wcs[128 + j]
               + eap[2] * wcs[256 + j] + eap[3] * wcs[384 + j];
            e1t[j * 68 + el] = fmaxf(v, 0.f);
        }
    }
    __syncthreads();

    // layer 2: thread = (edge-quad, col-quad); 4 edges x 4 cols register tile
    int mg = t & 15;                 // cols mg*4 .. mg*4+3
    int eg = t >> 4;                 // edges eg*4 .. eg*4+3
    float acc[4][4] = {};
    const float* ep = &e1t[eg * 4];
    const float* wp = &w2s[mg * 4];
#pragma unroll 4
    for (int jj = 0; jj < 128; jj++) {
        float4 ev = *reinterpret_cast<const float4*>(ep + jj * 68);
        float4 wv = *reinterpret_cast<const float4*>(wp + jj * 64);
        float er[4] = {ev.x, ev.y, ev.z, ev.w};
        float wr[4] = {wv.x, wv.y, wv.z, wv.w};
#pragma unroll
        for (int i = 0; i < 4; i++)
#pragma unroll
            for (int m = 0; m < 4; m++)
                acc[i][m] += er[i] * wr[m];
    }

    float be3v = be3[0];
    float s4[4];
#pragma unroll
    for (int i = 0; i < 4; i++) {
        float s = 0.f;
#pragma unroll
        for (int m = 0; m < 4; m++) {
            float l2 = fmaxf(acc[i][m] + b2s[mg * 4 + m], 0.f);
            s += l2 * w3s[mg * 4 + m];
        }
        s4[i] = s;
    }
#pragma unroll
    for (int i = 0; i < 4; i++) {
        s4[i] += __shfl_xor_sync(0xffffffffu, s4[i], 1);
        s4[i] += __shfl_xor_sync(0xffffffffu, s4[i], 2);
        s4[i] += __shfl_xor_sync(0xffffffffu, s4[i], 4);
        s4[i] += __shfl_xor_sync(0xffffffffu, s4[i], 8);
    }
    if (mg == 0) {
#pragma unroll
        for (int i = 0; i < 4; i++)
            out[e0 + eg * 4 + i] = s4[i] + be3v;
    }
}

// ---------------- launch ----------------
extern "C" void kernel_launch(void* const* d_in, const int* in_sizes, int n_in,
                              void* d_out, int out_size) {
    const float* x   = (const float*)d_in[0];
    const int*   ei  = (const int*)d_in[1];     // JAX x64 disabled -> int32
    const float* ea  = (const float*)d_in[2];
    const float* w1r = (const float*)d_in[3];
    const float* w1n = (const float*)d_in[4];
    const float* b1  = (const float*)d_in[5];
    const float* w2r = (const float*)d_in[6];
    const float* w2n = (const float*)d_in[7];
    const float* b2  = (const float*)d_in[8];
    const float* we1 = (const float*)d_in[9];
    const float* be1 = (const float*)d_in[10];
    const float* we2 = (const float*)d_in[11];
    const float* be2 = (const float*)d_in[12];
    const float* we3 = (const float*)d_in[13];
    const float* be3 = (const float*)d_in[14];
    float* out = (float*)d_out;

    cudaFuncSetAttribute(k_edge, cudaFuncAttributeMaxDynamicSharedMemorySize, 72192);

    k_zero<<<12500, 256>>>();
    k_agg1<<<N_EDGES / 256, 256>>>(x, ei);
    k_h1<<<N_NODES / 2, 256>>>(x, w1r, w1n, b1);
    k_agg2<<<N_EDGES / 8, 256>>>(ei);
    k_h2<<<dim3((N_NODES + 63) / 64, 2), 256>>>(w2r, w2n, b2);
    k_pq<<<dim3((N_NODES + 63) / 64, 2), 256>>>(we1);
    k_edge<<<N_EDGES / 64, 256, 72192>>>(ei, ea, we1, be1, we2, be2, we3, be3, out);
}

// round 4
// speedup vs baseline: 1.1747x; 1.1747x over previous
#include <cuda_runtime.h>

#define N_NODES 100000
#define N_EDGES 1600000
#define HID 128

// ---------------- scratch (device globals; no allocation) ----------------
__device__ float g_cnt [N_NODES];
__device__ float g_agg1[N_NODES * 6];
__device__ float g_h1  [N_NODES * HID];
__device__ float g_agg2[N_NODES * HID];
__device__ float g_h2  [N_NODES * HID];
__device__ float g_p   [N_NODES * HID];   // h2 @ W_e1[0:128]
__device__ float g_q   [N_NODES * HID];   // h2 @ W_e1[128:256]

// ---------------- packed fp32x2 helpers (sm_100+ fma.rn.f32x2) ----------------
__device__ __forceinline__ void fma2(unsigned long long& acc,
                                     unsigned long long a, unsigned long long b) {
    asm("fma.rn.f32x2 %0, %1, %2, %0;" : "+l"(acc) : "l"(a), "l"(b));
}
__device__ __forceinline__ unsigned long long dup2(float x) {
    unsigned long long r;
    unsigned int u = __float_as_uint(x);
    asm("mov.b64 %0, {%1, %1};" : "=l"(r) : "r"(u));
    return r;
}
__device__ __forceinline__ float2 unpk2(unsigned long long v) {
    float2 f;
    asm("mov.b64 {%0, %1}, %2;" : "=f"(f.x), "=f"(f.y) : "l"(v));
    return f;
}

// ---------------- zero scratch accumulators ----------------
__global__ void k_zero() {
    int i = blockIdx.x * 256 + threadIdx.x;            // grid covers 3.2M float4
    float4 z = make_float4(0.f, 0.f, 0.f, 0.f);
    if (i < N_NODES * HID / 4) reinterpret_cast<float4*>(g_agg2)[i] = z;
    if (i < N_NODES * 6 / 4)   reinterpret_cast<float4*>(g_agg1)[i] = z;
    if (i < N_NODES / 4)       reinterpret_cast<float4*>(g_cnt)[i]  = z;
}

// ---------------- SAGE layer 1: scatter x[src] into agg1, count ----------------
__global__ void k_agg1(const float* __restrict__ x, const int* __restrict__ ei) {
    int e = blockIdx.x * 256 + threadIdx.x;
    int s = ei[e];
    int d = ei[N_EDGES + e];
    atomicAdd(&g_cnt[d], 1.0f);
    // x rows are 6 floats = 24B -> every row is 8B-aligned; 3 vector reds
    const float2* xr = reinterpret_cast<const float2*>(x + s * 6);
    float* dst = &g_agg1[d * 6];
#pragma unroll
    for (int k = 0; k < 3; k++) {
        float2 v = xr[k];
        asm volatile("red.global.add.v2.f32 [%0], {%1, %2};"
                     :: "l"(dst + k * 2), "f"(v.x), "f"(v.y) : "memory");
    }
}

// ---------------- h1 = relu(x@W1r + mean1@W1n + b1) ----------------
__global__ void k_h1(const float* __restrict__ x,
                     const float* __restrict__ w1r, const float* __restrict__ w1n,
                     const float* __restrict__ b1) {
    int t = threadIdx.x;
    int node = blockIdx.x * 2 + (t >> 7);
    int j = t & 127;
    float inv = 1.0f / fmaxf(g_cnt[node], 1.0f);
    float acc = b1[j];
#pragma unroll
    for (int k = 0; k < 6; k++) {
        acc += x[node * 6 + k] * w1r[k * 128 + j]
             + g_agg1[node * 6 + k] * inv * w1n[k * 128 + j];
    }
    g_h1[node * 128 + j] = fmaxf(acc, 0.f);
}

// ---------------- scatter h1[src] into agg2 (warp per edge, vector red) ----------------
__global__ void k_agg2(const int* __restrict__ ei) {
    int w = blockIdx.x * 8 + (threadIdx.x >> 5);
    int lane = threadIdx.x & 31;
    int s = ei[w];
    int d = ei[N_EDGES + w];
    float4 v = *reinterpret_cast<const float4*>(&g_h1[s * 128 + lane * 4]);
    float* dst = &g_agg2[d * 128 + lane * 4];
    asm volatile("red.global.add.v4.f32 [%0], {%1, %2, %3, %4};"
                 :: "l"(dst), "f"(v.x), "f"(v.y), "f"(v.z), "f"(v.w) : "memory");
}

// ---------------- h2 = relu(h1@W2r + mean2@W2n + b2), dual-A GEMM ----------------
__global__ void k_h2(const float* __restrict__ W1, const float* __restrict__ W2,
                     const float* __restrict__ bias) {
    __shared__ __align__(16) float As1[16][64];
    __shared__ __align__(16) float As2[16][64];
    __shared__ __align__(16) float Bs1[16][64];
    __shared__ __align__(16) float Bs2[16][64];
    int t = threadIdx.x;
    int row0 = blockIdx.x * 64;
    int col0 = blockIdx.y * 64;
    int lnode = t >> 2;            // 0..63
    int lk4   = (t & 3) * 4;       // 0,4,8,12
    int lkB   = t >> 4;            // 0..15
    int ljB   = (t & 15) * 4;
    int tx = t & 15, ty = t >> 4;
    unsigned long long acc[4][2] = {};   // [row i][col-pair], f32x2

    for (int k0 = 0; k0 < 128; k0 += 16) {
        int row = row0 + lnode;
        float4 a1, a2;
        if (row < N_NODES) {
            a1 = *reinterpret_cast<const float4*>(&g_h1[row * 128 + k0 + lk4]);
            a2 = *reinterpret_cast<const float4*>(&g_agg2[row * 128 + k0 + lk4]);
            float inv = 1.0f / fmaxf(g_cnt[row], 1.0f);
            a2.x *= inv; a2.y *= inv; a2.z *= inv; a2.w *= inv;
        } else {
            a1 = a2 = make_float4(0.f, 0.f, 0.f, 0.f);
        }
        As1[lk4 + 0][lnode] = a1.x; As1[lk4 + 1][lnode] = a1.y;
        As1[lk4 + 2][lnode] = a1.z; As1[lk4 + 3][lnode] = a1.w;
        As2[lk4 + 0][lnode] = a2.x; As2[lk4 + 1][lnode] = a2.y;
        As2[lk4 + 2][lnode] = a2.z; As2[lk4 + 3][lnode] = a2.w;
        *reinterpret_cast<float4*>(&Bs1[lkB][ljB]) =
            *reinterpret_cast<const float4*>(&W1[(k0 + lkB) * 128 + col0 + ljB]);
        *reinterpret_cast<float4*>(&Bs2[lkB][ljB]) =
            *reinterpret_cast<const float4*>(&W2[(k0 + lkB) * 128 + col0 + ljB]);
        __syncthreads();
#pragma unroll
        for (int kk = 0; kk < 16; kk++) {
            float4 a1v = *reinterpret_cast<float4*>(&As1[kk][ty * 4]);
            float4 a2v = *reinterpret_cast<float4*>(&As2[kk][ty * 4]);
            ulonglong2 b1v = *reinterpret_cast<ulonglong2*>(&Bs1[kk][tx * 4]);
            ulonglong2 b2v = *reinterpret_cast<ulonglong2*>(&Bs2[kk][tx * 4]);
            unsigned long long a1d[4] = {dup2(a1v.x), dup2(a1v.y), dup2(a1v.z), dup2(a1v.w)};
            unsigned long long a2d[4] = {dup2(a2v.x), dup2(a2v.y), dup2(a2v.z), dup2(a2v.w)};
#pragma unroll
            for (int i = 0; i < 4; i++) {
                fma2(acc[i][0], a1d[i], b1v.x);
                fma2(acc[i][0], a2d[i], b2v.x);
                fma2(acc[i][1], a1d[i], b1v.y);
                fma2(acc[i][1], a2d[i], b2v.y);
            }
        }
        __syncthreads();
    }

    int row = row0 + ty * 4;
    int col = col0 + tx * 4;
#pragma unroll
    for (int i = 0; i < 4; i++) {
        if (row + i < N_NODES) {
            float2 lo = unpk2(acc[i][0]);
            float2 hi = unpk2(acc[i][1]);
            float4 c;
            c.x = fmaxf(lo.x + bias[col + 0], 0.f);
            c.y = fmaxf(lo.y + bias[col + 1], 0.f);
            c.z = fmaxf(hi.x + bias[col + 2], 0.f);
            c.w = fmaxf(hi.y + bias[col + 3], 0.f);
            *reinterpret_cast<float4*>(&g_h2[(row + i) * 128 + col]) = c;
        }
    }
}

// ---------------- p = h2@W_a, q = h2@W_b (single-A dual-B GEMM) ----------------
__global__ void k_pq(const float* __restrict__ we1) {
    __shared__ __align__(16) float As[16][64];
    __shared__ __align__(16) float Bs1[16][64];
    __shared__ __align__(16) float Bs2[16][64];
    int t = threadIdx.x;
    int row0 = blockIdx.x * 64;
    int col0 = blockIdx.y * 64;
    int lnode = t >> 2;
    int lk4   = (t & 3) * 4;
    int lkB   = t >> 4;
    int ljB   = (t & 15) * 4;
    int tx = t & 15, ty = t >> 4;
    unsigned long long acc1[4][2] = {};
    unsigned long long acc2[4][2] = {};

    for (int k0 = 0; k0 < 128; k0 += 16) {
        int row = row0 + lnode;
        float4 a;
        if (row < N_NODES)
            a = *reinterpret_cast<const float4*>(&g_h2[row * 128 + k0 + lk4]);
        else
            a = make_float4(0.f, 0.f, 0.f, 0.f);
        As[lk4 + 0][lnode] = a.x; As[lk4 + 1][lnode] = a.y;
        As[lk4 + 2][lnode] = a.z; As[lk4 + 3][lnode] = a.w;
        // W_a = rows [0,128), W_b = rows [128,256) of w_e1 (260x128 row-major)
        *reinterpret_cast<float4*>(&Bs1[lkB][ljB]) =
            *reinterpret_cast<const float4*>(&we1[(k0 + lkB) * 128 + col0 + ljB]);
        *reinterpret_cast<float4*>(&Bs2[lkB][ljB]) =
            *reinterpret_cast<const float4*>(&we1[(128 + k0 + lkB) * 128 + col0 + ljB]);
        __syncthreads();
#pragma unroll
        for (int kk = 0; kk < 16; kk++) {
            float4 av  = *reinterpret_cast<float4*>(&As[kk][ty * 4]);
            ulonglong2 b1v = *reinterpret_cast<ulonglong2*>(&Bs1[kk][tx * 4]);
            ulonglong2 b2v = *reinterpret_cast<ulonglong2*>(&Bs2[kk][tx * 4]);
            unsigned long long ad[4] = {dup2(av.x), dup2(av.y), dup2(av.z), dup2(av.w)};
#pragma unroll
            for (int i = 0; i < 4; i++) {
                fma2(acc1[i][0], ad[i], b1v.x);
                fma2(acc1[i][1], ad[i], b1v.y);
                fma2(acc2[i][0], ad[i], b2v.x);
                fma2(acc2[i][1], ad[i], b2v.y);
            }
        }
        __syncthreads();
    }

    int row = row0 + ty * 4;
    int col = col0 + tx * 4;
#pragma unroll
    for (int i = 0; i < 4; i++) {
        if (row + i < N_NODES) {
            float2 p0 = unpk2(acc1[i][0]), p1 = unpk2(acc1[i][1]);
            float2 q0 = unpk2(acc2[i][0]), q1 = unpk2(acc2[i][1]);
            *reinterpret_cast<float4*>(&g_p[(row + i) * 128 + col]) =
                make_float4(p0.x, p0.y, p1.x, p1.y);
            *reinterpret_cast<float4*>(&g_q[(row + i) * 128 + col]) =
                make_float4(q0.x, q0.y, q1.x, q1.y);
        }
    }
}

// ---------------- fused edge MLP: 64 edges per block ----------------
// e1 = relu(p[src] + q[dst] + ea@W_c + b_e1)  -> smem transposed [j][edge]
// l2 = relu(e1 @ w_e2 + b_e2); out = l2 @ w_e3 + b_e3
__global__ void k_edge(const int* __restrict__ ei, const float* __restrict__ ea,
                       const float* __restrict__ we1, const float* __restrict__ be1,
                       const float* __restrict__ we2, const float* __restrict__ be2,
                       const float* __restrict__ we3, const float* __restrict__ be3,
                       float* __restrict__ out) {
    extern __shared__ __align__(16) float sm[];
    float* w2s = sm;                 // [128][64]         8192 floats
    float* e1t = sm + 8192;          // [128][68] padded  8704 floats
    float* wcs = e1t + 8704;         // [4][128]           512
    float* b1s = wcs + 512;          // 128
    float* b2s = b1s + 128;          // 64
    float* w3s = b2s + 64;           // 64
    float* eas = w3s + 64;           // [64][4]            256
    int*   srcs = reinterpret_cast<int*>(eas + 256);  // 64
    int*   dsts = srcs + 64;                          // 64

    int t = threadIdx.x;
    int e0 = blockIdx.x * 64;

    for (int i = t; i < 8192; i += 256) w2s[i] = we2[i];
    for (int i = t; i < 512;  i += 256) wcs[i] = we1[256 * 128 + i];
    if (t < 128) b1s[t] = be1[t];
    if (t < 64) { b2s[t] = be2[t]; w3s[t] = we3[t]; }
    if (t < 64)        srcs[t]      = ei[e0 + t];
    else if (t < 128)  dsts[t - 64] = ei[N_EDGES + e0 + (t - 64)];
    eas[t] = ea[e0 * 4 + t];        // 256 threads cover 64*4
    __syncthreads();

    // e1 phase: 128 threads per edge-pair, coalesced gathers of p/q rows
    {
        int j = t & 127;
        for (int el = t >> 7; el < 64; el += 2) {
            int s = srcs[el], d = dsts[el];
            float v = g_p[s * 128 + j] + g_q[d * 128 + j] + b1s[j];
            const float* eap = &eas[el * 4];
            v += eap[0] * wcs[j]       + eap[1] * wcs[128 + j]
               + eap[2] * wcs[256 + j] + eap[3] * wcs[384 + j];
            e1t[j * 68 + el] = fmaxf(v, 0.f);
        }
    }
    __syncthreads();

    // layer 2: thread = (edge-quad, col-quad); 4 edges x 4 cols, packed f32x2
    int mg = t & 15;                 // cols mg*4 .. mg*4+3
    int eg = t >> 4;                 // edges eg*4 .. eg*4+3
    unsigned long long acc[4][2] = {};   // [edge i][col-pair]
    const float* ep = &e1t[eg * 4];
    const float* wp = &w2s[mg * 4];
#pragma unroll 4
    for (int jj = 0; jj < 128; jj++) {
        float4 ev = *reinterpret_cast<const float4*>(ep + jj * 68);
        ulonglong2 wv = *reinterpret_cast<const ulonglong2*>(wp + jj * 64);
        unsigned long long ed[4] = {dup2(ev.x), dup2(ev.y), dup2(ev.z), dup2(ev.w)};
#pragma unroll
        for (int i = 0; i < 4; i++) {
            fma2(acc[i][0], ed[i], wv.x);
            fma2(acc[i][1], ed[i], wv.y);
        }
    }

    float be3v = be3[0];
    float s4[4];
#pragma unroll
    for (int i = 0; i < 4; i++) {
        float2 lo = unpk2(acc[i][0]);
        float2 hi = unpk2(acc[i][1]);
        float c0 = fmaxf(lo.x + b2s[mg * 4 + 0], 0.f);
        float c1 = fmaxf(lo.y + b2s[mg * 4 + 1], 0.f);
        float c2 = fmaxf(hi.x + b2s[mg * 4 + 2], 0.f);
        float c3 = fmaxf(hi.y + b2s[mg * 4 + 3], 0.f);
        s4[i] = c0 * w3s[mg * 4 + 0] + c1 * w3s[mg * 4 + 1]
              + c2 * w3s[mg * 4 + 2] + c3 * w3s[mg * 4 + 3];
    }
#pragma unroll
    for (int i = 0; i < 4; i++) {
        s4[i] += __shfl_xor_sync(0xffffffffu, s4[i], 1);
        s4[i] += __shfl_xor_sync(0xffffffffu, s4[i], 2);
        s4[i] += __shfl_xor_sync(0xffffffffu, s4[i], 4);
        s4[i] += __shfl_xor_sync(0xffffffffu, s4[i], 8);
    }
    if (mg == 0) {
#pragma unroll
        for (int i = 0; i < 4; i++)
            out[e0 + eg * 4 + i] = s4[i] + be3v;
    }
}

// ---------------- launch ----------------
extern "C" void kernel_launch(void* const* d_in, const int* in_sizes, int n_in,
                              void* d_out, int out_size) {
    const float* x   = (const float*)d_in[0];
    const int*   ei  = (const int*)d_in[1];     // JAX x64 disabled -> int32
    const float* ea  = (const float*)d_in[2];
    const float* w1r = (const float*)d_in[3];
    const float* w1n = (const float*)d_in[4];
    const float* b1  = (const float*)d_in[5];
    const float* w2r = (const float*)d_in[6];
    const float* w2n = (const float*)d_in[7];
    const float* b2  = (const float*)d_in[8];
    const float* we1 = (const float*)d_in[9];
    const float* be1 = (const float*)d_in[10];
    const float* we2 = (const float*)d_in[11];
    const float* be2 = (const float*)d_in[12];
    const float* we3 = (const float*)d_in[13];
    const float* be3 = (const float*)d_in[14];
    float* out = (float*)d_out;

    cudaFuncSetAttribute(k_edge, cudaFuncAttributeMaxDynamicSharedMemorySize, 72192);

    k_zero<<<12500, 256>>>();
    k_agg1<<<N_EDGES / 256, 256>>>(x, ei);
    k_h1<<<N_NODES / 2, 256>>>(x, w1r, w1n, b1);
    k_agg2<<<N_EDGES / 8, 256>>>(ei);
    k_h2<<<dim3((N_NODES + 63) / 64, 2), 256>>>(w2r, w2n, b2);
    k_pq<<<dim3((N_NODES + 63) / 64, 2), 256>>>(we1);
    k_edge<<<N_EDGES / 64, 256, 72192>>>(ei, ea, we1, be1, we2, be2, we3, be3, out);
}